// round 16
// baseline (speedup 1.0000x reference)
#include <cuda_runtime.h>
#include <cstdint>

// InteractionArch: out[b] = concat(dense[b] (128), sparse[b]·dense[b] (26),
//                                  triu_{k=1}(sparse[b]·sparse[b]^T) (325))
// B=16384, F=26, D=128, out stride 479 fp32 (row base only 4B-aligned).
//
// R16: R15 with the dense-stride bug fixed (per-lane source stride: sparse
// lanes advance by NF*DD per batch row, dense lane by DD) and fill(c+1)
// moved after the chunk-c wait (+syncwarp) to make buffer reuse airtight.
// Per-lane cp.async.bulk fill (128B/vector chunk), double-buffered, 7x7
// register tiles, 3 rows/warp, conflict-free rotated LDS.128, scalar FMA,
// 21.5KB smem -> 10 single-warp blocks/SM.

#define B_TOT 16384
#define NF 26
#define DD 128
#define NV 28
#define CHUNK 32          // floats per k-chunk
#define CQ 8              // float4 quads per chunk
#define NCH 4             // chunks (128/32)
#define OUT_STRIDE 479
#define RPW 3             // batch rows per warp
#define CB 128            // bulk bytes per vector chunk (32 floats)

__device__ __forceinline__ uint32_t smem_u32(const void* p) {
    uint32_t a;
    asm("{ .reg .u64 t; cvta.to.shared.u64 t, %1; cvt.u32.u64 %0, t; }" : "=r"(a) : "l"(p));
    return a;
}
__device__ __forceinline__ void bulk_ld(uint32_t dst, const void* src,
                                        uint32_t bytes, uint32_t mbar) {
    asm volatile(
        "cp.async.bulk.shared::cta.global.mbarrier::complete_tx::bytes "
        "[%0], [%1], %2, [%3];"
        :: "r"(dst), "l"(src), "r"(bytes), "r"(mbar) : "memory");
}
__device__ __forceinline__ void mbar_wait(uint32_t mbar, uint32_t parity) {
    uint32_t done;
    asm volatile(
        "{\n\t.reg .pred p;\n\t"
        "mbarrier.try_wait.parity.acquire.cta.shared::cta.b64 p, [%1], %2;\n\t"
        "selp.b32 %0, 1, 0, p;\n\t}"
        : "=r"(done) : "r"(mbar), "r"(parity) : "memory");
    if (!done) {
        asm volatile(
            "{\n\t.reg .pred P1;\n\t"
            "WL_%=:\n\t"
            "mbarrier.try_wait.parity.acquire.cta.shared::cta.b64 P1, [%0], %1, 0x989680;\n\t"
            "@P1 bra.uni WD_%=;\n\t"
            "bra.uni WL_%=;\n\t"
            "WD_%=:\n\t}"
            :: "r"(mbar), "r"(parity) : "memory");
    }
}

__global__ void __launch_bounds__(32, 10) interact_kernel(
    const float* __restrict__ dense,
    const float* __restrict__ sparse,
    float* __restrict__ out)
{
    __shared__ float Xs[RPW][2][NV][CHUNK];            // 21504 B
    __shared__ __align__(8) unsigned long long mbar_s[2];

    const int lane = threadIdx.x;
    const int b0   = blockIdx.x * RPW;
    const uint32_t mb0 = smem_u32(&mbar_s[0]);
    const uint32_t mb1 = smem_u32(&mbar_s[1]);

    // ---- init mbarriers ----
    if (lane == 0) {
        asm volatile("mbarrier.init.shared.b64 [%0], %1;" :: "r"(mb0), "r"(1u) : "memory");
        asm volatile("mbarrier.init.shared.b64 [%0], %1;" :: "r"(mb1), "r"(1u) : "memory");
    }

    // ---- zero pad row 27 (both buffers; fills never touch it) ----
    #pragma unroll
    for (int t = 0; t < 2; t++) {
        int idx = lane + 32 * t;               // RPW*2*8 = 48 float4
        if (idx < RPW * 2 * 8) {
            int rr  = idx / 16;
            int rem = idx - rr * 16;
            reinterpret_cast<float4*>(&Xs[rr][rem / 8][27][0])[rem & 7] =
                make_float4(0.f, 0.f, 0.f, 0.f);
        }
    }
    __syncwarp();

    // how many rows valid (tail block)
    int nvalid = 0;
    #pragma unroll
    for (int r = 0; r < RPW; r++)
        if (b0 + r < B_TOT) nvalid++;
    const uint32_t tx_bytes = (uint32_t)nvalid * 27u * CB;

    // per-lane fill source + PER-LANE batch-row stride (the R15 bug):
    // sparse lanes step NF*DD per row, the dense lane steps DD.
    const float* __restrict__ vsrc =
        (lane < NF) ? sparse + (size_t)b0 * NF * DD + (size_t)lane * DD
                    : dense + (size_t)b0 * DD;      // lane 26
    const size_t vstride = (lane < NF) ? (size_t)NF * DD : (size_t)DD;

    // ---- chunk fill: expect_tx (lane 0) then per-lane bulk copies ----
    auto fill = [&](int c, int buf) {
        const uint32_t mb = buf ? mb1 : mb0;
        if (lane == 0) {
            asm volatile("mbarrier.arrive.expect_tx.shared.b64 _, [%0], %1;"
                         :: "r"(mb), "r"(tx_bytes) : "memory");
        }
        __syncwarp();
        if (lane < 27) {
            #pragma unroll
            for (int r = 0; r < RPW; r++) {
                if (b0 + r < B_TOT) {
                    const float* g = vsrc + (size_t)r * vstride + c * CHUNK;
                    bulk_ld(smem_u32(&Xs[r][buf][lane][0]), g, CB, mb);
                }
            }
        }
    };

    fill(0, 0);

    // ---- dense passthrough (overlaps chunk 0 DMA) ----
    #pragma unroll
    for (int r = 0; r < RPW; r++) {
        const int b = b0 + r;
        if (b >= B_TOT) break;
        float4 dv = reinterpret_cast<const float4*>(dense + (size_t)b * DD)[lane];
        float* ob = out + (size_t)b * OUT_STRIDE;
        ob[4 * lane + 0] = dv.x;
        ob[4 * lane + 1] = dv.y;
        ob[4 * lane + 2] = dv.z;
        ob[4 * lane + 3] = dv.w;
    }

    // ---- lane -> (row, tile): 3 rows x 10 upper-tri 7x7 tiles ----
    const int r  = lane / 10;                  // 0..2 (lanes 30,31 idle)
    const int t  = lane - r * 10;              // 0..9
    const int bc = b0 + r;
    const bool active = (lane < 30) && (bc < B_TOT);

    const int ti = (t < 4) ? 0 : (t < 7) ? 1 : (t < 9) ? 2 : 3;
    const int tj = (t < 4) ? t : (t < 7) ? t - 3 : (t < 9) ? t - 5 : 3;

    float acc[7][7];
    #pragma unroll
    for (int ii = 0; ii < 7; ii++)
        #pragma unroll
        for (int jj = 0; jj < 7; jj++)
            acc[ii][jj] = 0.f;

    // ---- pipelined chunk loop: wait chunk c, then launch fill c+1 into the
    // buffer consumed at c-1 (safe: that read pass ended at previous iter's
    // trailing syncwarp) ----
    #pragma unroll
    for (int c = 0; c < NCH; c++) {
        const int buf = c & 1;
        mbar_wait(buf ? mb1 : mb0, (uint32_t)((c >> 1) & 1));
        __syncwarp();
        if (c + 1 < NCH) fill(c + 1, buf ^ 1);

        if (active) {
            const float4* __restrict__ pi4 =
                reinterpret_cast<const float4*>(&Xs[r][buf][7 * ti][0]);
            const float4* __restrict__ pj4 =
                reinterpret_cast<const float4*>(&Xs[r][buf][7 * tj][0]);
            #pragma unroll
            for (int kk = 0; kk < CQ; kk++) {
                const int kq = (kk + lane) & (CQ - 1);
                float4 xi[7], xj[7];
                #pragma unroll
                for (int ii = 0; ii < 7; ii++) xi[ii] = pi4[ii * CQ + kq];
                #pragma unroll
                for (int jj = 0; jj < 7; jj++) xj[jj] = pj4[jj * CQ + kq];
                #pragma unroll
                for (int ii = 0; ii < 7; ii++)
                    #pragma unroll
                    for (int jj = 0; jj < 7; jj++) {
                        float s = acc[ii][jj];
                        s = fmaf(xi[ii].x, xj[jj].x, s);
                        s = fmaf(xi[ii].y, xj[jj].y, s);
                        s = fmaf(xi[ii].z, xj[jj].z, s);
                        s = fmaf(xi[ii].w, xj[jj].w, s);
                        acc[ii][jj] = s;
                    }
            }
        }
        __syncwarp();   // all lanes done reading buf before it is refilled
    }

    // ---- epilogue: scatter needed dots (i<j, j<=26) ----
    if (!active) return;
    float* ob = out + (size_t)bc * OUT_STRIDE;
    #pragma unroll
    for (int ii = 0; ii < 7; ii++) {
        #pragma unroll
        for (int jj = 0; jj < 7; jj++) {
            const int i = 7 * ti + ii;
            const int j = 7 * tj + jj;
            if (i < j && j <= 26) {
                int dst;
                if (j == 26) {
                    dst = 128 + i;                                        // sparse·dense
                } else {
                    dst = 154 + i * 25 - (i * (i - 1)) / 2 + (j - i - 1); // pair
                }
                ob[dst] = acc[ii][jj];
            }
        }
    }
}

extern "C" void kernel_launch(void* const* d_in, const int* in_sizes, int n_in,
                              void* d_out, int out_size)
{
    (void)n_in; (void)out_size;
    const float* a = (const float*)d_in[0];
    const float* b = (const float*)d_in[1];
    // dense has B*D = 2,097,152 elems; sparse has B*F*D = 54,525,952 elems.
    const float* dense  = (in_sizes[0] < in_sizes[1]) ? a : b;
    const float* sparse = (in_sizes[0] < in_sizes[1]) ? b : a;

    const int grid = (B_TOT + RPW - 1) / RPW;
    interact_kernel<<<grid, 32>>>(dense, sparse, (float*)d_out);
}

// round 17
// speedup vs baseline: 1.7657x; 1.7657x over previous
#include <cuda_runtime.h>
#include <cstdint>

// InteractionArch: out[b] = concat(dense[b] (128), sparse[b]·dense[b] (26),
//                                  triu_{k=1}(sparse[b]·sparse[b]^T) (325))
// B=16384, F=26, D=128, out stride 479 fp32 (row base only 4B-aligned).
//
// R17: 3xTF32 mma.sync Gram. One warp per batch row. X (28x128 fp32, padded
// to 32 rows) in smem with XOR swizzle k^((row&7)<<2) -> conflict-free
// fragment LDS.32. Split x = hi + lo (cvt.rna.tf32); G ~= hi*hi^T + hi*lo^T
// + lo*hi^T accumulated in fp32 via mma.sync.m16n8k8. 6 of 8 MxN tile
// positions (upper-tri), 16 K-tiles, 288 HMMA/row. 4 warps/block, 64KB smem
// -> 3 blocks/SM (12 warps). MACs leave the saturated scalar-FMA pipe.

#define B_TOT 16384
#define NF 26
#define DD 128
#define OUT_STRIDE 479
#define WPB 4              // warps per block (1 batch row each)

__device__ __forceinline__ uint32_t f2tf(float x) {
    uint32_t r;
    asm("cvt.rna.tf32.f32 %0, %1;" : "=r"(r) : "f"(x));
    return r;
}
__device__ __forceinline__ void mma_tf32(float* d, const uint32_t* a,
                                         const uint32_t* b) {
    asm volatile(
        "mma.sync.aligned.m16n8k8.row.col.f32.tf32.tf32.f32 "
        "{%0,%1,%2,%3}, {%4,%5,%6,%7}, {%8,%9}, {%0,%1,%2,%3};"
        : "+f"(d[0]), "+f"(d[1]), "+f"(d[2]), "+f"(d[3])
        : "r"(a[0]), "r"(a[1]), "r"(a[2]), "r"(a[3]), "r"(b[0]), "r"(b[1]));
}

__global__ void __launch_bounds__(WPB * 32, 3) interact_kernel(
    const float* __restrict__ dense,
    const float* __restrict__ sparse,
    float* __restrict__ out)
{
    __shared__ float Xs[WPB][32][DD];      // 65536 B

    const int tid  = threadIdx.x;
    const int w    = tid >> 5;
    const int lane = tid & 31;
    const int b    = blockIdx.x * WPB + w; // this warp's batch row
    const int g    = lane >> 2;            // groupID 0..7
    const int tig  = lane & 3;             // thread-in-group 0..3

    // ---- fill: rows 0..25 sparse, 26 dense, 27..31 zero; XOR-swizzled ----
    const float* __restrict__ spb = sparse + (size_t)b * NF * DD;
    const float* __restrict__ dnb = dense + (size_t)b * DD;
    float4 dv;                             // keep dense row for passthrough
    #pragma unroll
    for (int t = 0; t < 32; t++) {
        float4 v = make_float4(0.f, 0.f, 0.f, 0.f);
        if (t < 26)       v = *reinterpret_cast<const float4*>(spb + t * DD + 4 * lane);
        else if (t == 26) { v = *reinterpret_cast<const float4*>(dnb + 4 * lane); dv = v; }
        const int ks = (4 * lane) ^ ((t & 7) << 2);   // float4-aligned swizzle
        *reinterpret_cast<float4*>(&Xs[w][t][ks]) = v;
    }
    // dense passthrough to out[0:128] (scalar stores; base only 4B-aligned)
    {
        float* ob = out + (size_t)b * OUT_STRIDE;
        ob[4 * lane + 0] = dv.x;
        ob[4 * lane + 1] = dv.y;
        ob[4 * lane + 2] = dv.z;
        ob[4 * lane + 3] = dv.w;
    }
    __syncwarp();

    // ---- 6 needed tile positions (mt, nt): rows 16mt.., cols 8nt.. ----
    // (0,0)(0,1)(0,2)(0,3)(1,2)(1,3)
    float d0[4] = {0,0,0,0}, d1[4] = {0,0,0,0}, d2[4] = {0,0,0,0};
    float d3[4] = {0,0,0,0}, d4[4] = {0,0,0,0}, d5[4] = {0,0,0,0};

    const uint32_t swl = (uint32_t)(g << 2);   // row&7 == g for all frag rows

    #pragma unroll 4
    for (int kt = 0; kt < 16; kt++) {
        // A fragments, mt = 0,1: a[i] = X[16mt + g + 8*(i&1)][tig + 4*(i>>1) + 8kt]
        uint32_t ah[2][4], al[2][4];
        #pragma unroll
        for (int mt = 0; mt < 2; mt++) {
            #pragma unroll
            for (int i = 0; i < 4; i++) {
                const int row = 16 * mt + g + 8 * (i & 1);
                const int k   = (tig + 4 * (i >> 1) + 8 * kt) ^ swl;
                const float x = Xs[w][row][k];
                const uint32_t h = f2tf(x);
                ah[mt][i] = h;
                al[mt][i] = f2tf(x - __uint_as_float(h));
            }
        }
        // B fragments, nt = 0..3: b[i] = X[8nt + g][tig + 4*i + 8kt]
        uint32_t bh[4][2], bl[4][2];
        #pragma unroll
        for (int nt = 0; nt < 4; nt++) {
            #pragma unroll
            for (int i = 0; i < 2; i++) {
                const int n = 8 * nt + g;
                const int k = (tig + 4 * i + 8 * kt) ^ swl;
                const float x = Xs[w][n][k];
                const uint32_t h = f2tf(x);
                bh[nt][i] = h;
                bl[nt][i] = f2tf(x - __uint_as_float(h));
            }
        }
        // 3-term accumulate per position
        mma_tf32(d0, ah[0], bh[0]); mma_tf32(d0, ah[0], bl[0]); mma_tf32(d0, al[0], bh[0]);
        mma_tf32(d1, ah[0], bh[1]); mma_tf32(d1, ah[0], bl[1]); mma_tf32(d1, al[0], bh[1]);
        mma_tf32(d2, ah[0], bh[2]); mma_tf32(d2, ah[0], bl[2]); mma_tf32(d2, al[0], bh[2]);
        mma_tf32(d3, ah[0], bh[3]); mma_tf32(d3, ah[0], bl[3]); mma_tf32(d3, al[0], bh[3]);
        mma_tf32(d4, ah[1], bh[2]); mma_tf32(d4, ah[1], bl[2]); mma_tf32(d4, al[1], bh[2]);
        mma_tf32(d5, ah[1], bh[3]); mma_tf32(d5, ah[1], bl[3]); mma_tf32(d5, al[1], bh[3]);
    }

    // ---- epilogue: scatter i<j<=26 from D fragments ----
    // D(mt,nt): d[2*half+cc] = G[16mt + g + 8*half][8nt + 2*tig + cc]
    float* ob = out + (size_t)b * OUT_STRIDE;
    const float* dp[6] = {d0, d1, d2, d3, d4, d5};
    const int PM[6] = {0, 0, 0, 0, 1, 1};
    const int PN[6] = {0, 1, 2, 3, 2, 3};
    #pragma unroll
    for (int p = 0; p < 6; p++) {
        #pragma unroll
        for (int half = 0; half < 2; half++) {
            const int i = 16 * PM[p] + g + 8 * half;
            #pragma unroll
            for (int cc = 0; cc < 2; cc++) {
                const int j = 8 * PN[p] + 2 * tig + cc;
                if (i < j && j <= 26) {
                    int dst;
                    if (j == 26) {
                        dst = 128 + i;                                        // sparse·dense
                    } else {
                        dst = 154 + i * 25 - (i * (i - 1)) / 2 + (j - i - 1); // pair
                    }
                    ob[dst] = dp[p][2 * half + cc];
                }
            }
        }
    }
}

extern "C" void kernel_launch(void* const* d_in, const int* in_sizes, int n_in,
                              void* d_out, int out_size)
{
    (void)n_in; (void)out_size;
    const float* a = (const float*)d_in[0];
    const float* b = (const float*)d_in[1];
    // dense has B*D = 2,097,152 elems; sparse has B*F*D = 54,525,952 elems.
    const float* dense  = (in_sizes[0] < in_sizes[1]) ? a : b;
    const float* sparse = (in_sizes[0] < in_sizes[1]) ? b : a;

    interact_kernel<<<B_TOT / WPB, WPB * 32>>>(dense, sparse, (float*)d_out);
}